// round 6
// baseline (speedup 1.0000x reference)
#include <cuda_runtime.h>
#include <cstdint>

#define NODES   16384
#define NPG     128
#define NG      128
#define HID     128
#define KNN     24

typedef unsigned long long u64;

// ---------------- scratch ----------------
__device__ float g_feat_a[NODES * HID];
__device__ float g_feat_b[NODES * HID];
__device__ float g_pq[NODES * 2 * HID];
__device__ float g_wc[HID * 2 * HID];

__device__ __forceinline__ float elu_fast(float v) {
    return v > 0.0f ? v : (__expf(v) - 1.0f);
}

__device__ __forceinline__ unsigned fkey(float v) {
    unsigned b = __float_as_uint(v);
    return b ^ ((b & 0x80000000u) ? 0xffffffffu : 0x80000000u);
}

// ---- packed fp32x2 helpers (sm_103a FFMA2) ----
__device__ __forceinline__ u64 pack2(float lo, float hi) {
    u64 r; asm("mov.b64 %0,{%1,%2};" : "=l"(r) : "f"(lo), "f"(hi)); return r;
}
__device__ __forceinline__ void unpack2(u64 v, float& lo, float& hi) {
    asm("mov.b64 {%0,%1},%2;" : "=f"(lo), "=f"(hi) : "l"(v));
}
__device__ __forceinline__ void dfma(u64& d, u64 a, u64 b) {
    asm("fma.rn.f32x2 %0,%1,%2,%0;" : "+l"(d) : "l"(a), "l"(b));
}

// ---- cp.async helpers ----
__device__ __forceinline__ void cp16(void* smem, const void* gmem) {
    unsigned s = (unsigned)__cvta_generic_to_shared(smem);
    asm volatile("cp.async.cg.shared.global [%0], [%1], 16;\n" :: "r"(s), "l"(gmem));
}
__device__ __forceinline__ void cp_commit() { asm volatile("cp.async.commit_group;\n"); }
__device__ __forceinline__ void cp_wait0()  { asm volatile("cp.async.wait_group 0;\n"); }

// ---------------- pipelined 128x128-tile fp32 matmul (FFMA2, dup-A) --------
// A: MxK row-major, B: KxN row-major, C: MxN. M%128==0, N%128==0, K%16==0.
// As2 holds A values duplicated as f32x2; acc pairs run over COLUMN pairs, so
// the B operand is a natural float2 from Bs (no MOV duplication in the loop).
#define SAD 134   // u64 stride of an As2 row (even -> 16B-aligned vector loads)
#define MM_SMEM (2*16*SAD*8 + 2*16*128*4)

__global__ __launch_bounds__(256, 2) void mm_kernel(
    const float* __restrict__ A, const float* __restrict__ B,
    const float* __restrict__ bias, int biasLimit, int doElu,
    float* __restrict__ C, int M, int N, int K)
{
    extern __shared__ char smraw[];
    u64*   As2 = (u64*)smraw;                    // [2][16*SAD] duplicated A
    float* Bs  = (float*)(As2 + 2 * 16 * SAD);   // [2][16*128]

    const int tid = threadIdx.x;
    const int tx = tid & 15;
    const int ty = tid >> 4;
    const int rowBase = blockIdx.x * 128;
    const int colBase = blockIdx.y * 128;

    u64 acc2[8][4];   // [row][colpair]: (C[row][2c], C[row][2c+1])
#pragma unroll
    for (int r = 0; r < 8; r++)
#pragma unroll
        for (int c = 0; c < 4; c++) acc2[r][c] = 0ull;

    int am[8], ak[8];
#pragma unroll
    for (int t = 0; t < 8; t++) {
        int idx = t * 256 + tid;
        am[t] = idx >> 4; ak[t] = idx & 15;
    }
    int bk[2], bn[2];
#pragma unroll
    for (int t = 0; t < 2; t++) {
        int idx = t * 256 + tid;            // 0..511
        bk[t] = idx >> 5;                   // 0..15
        bn[t] = (idx & 31) * 4;             // 0..124
    }

    float aReg[8];
    // prologue
#pragma unroll
    for (int t = 0; t < 8; t++)
        aReg[t] = A[(size_t)(rowBase + am[t]) * K + ak[t]];
#pragma unroll
    for (int t = 0; t < 2; t++)
        cp16(&Bs[bk[t] * 128 + bn[t]], &B[(size_t)bk[t] * N + colBase + bn[t]]);
    cp_commit();
#pragma unroll
    for (int t = 0; t < 8; t++)
        As2[ak[t] * SAD + am[t]] = pack2(aReg[t], aReg[t]);
    cp_wait0();
    __syncthreads();

    int buf = 0;
    for (int kk = 0; kk < K; kk += 16) {
        const int nkk = kk + 16;
        if (nkk < K) {
#pragma unroll
            for (int t = 0; t < 8; t++)
                aReg[t] = A[(size_t)(rowBase + am[t]) * K + nkk + ak[t]];
#pragma unroll
            for (int t = 0; t < 2; t++)
                cp16(&Bs[(buf ^ 1) * 2048 + bk[t] * 128 + bn[t]],
                     &B[(size_t)(nkk + bk[t]) * N + colBase + bn[t]]);
            cp_commit();
        }

        const u64*   Asb = As2 + buf * 16 * SAD;
        const float* Bsb = Bs  + buf * 2048;
#pragma unroll
        for (int k = 0; k < 16; k++) {
            const u64* ap = Asb + k * SAD + ty * 8;
            ulonglong2 a01 = *(const ulonglong2*)(ap);
            ulonglong2 a23 = *(const ulonglong2*)(ap + 2);
            ulonglong2 a45 = *(const ulonglong2*)(ap + 4);
            ulonglong2 a67 = *(const ulonglong2*)(ap + 6);
            u64 a[8] = {a01.x, a01.y, a23.x, a23.y, a45.x, a45.y, a67.x, a67.y};
            const float* bp = Bsb + k * 128 + tx * 8;
            ulonglong2 b03 = *(const ulonglong2*)(bp);      // (c0,c1),(c2,c3)
            ulonglong2 b47 = *(const ulonglong2*)(bp + 4);  // (c4,c5),(c6,c7)
            u64 b[4] = {b03.x, b03.y, b47.x, b47.y};
#pragma unroll
            for (int r = 0; r < 8; r++)
#pragma unroll
                for (int c = 0; c < 4; c++) dfma(acc2[r][c], a[r], b[c]);
        }

        if (nkk < K) {
#pragma unroll
            for (int t = 0; t < 8; t++)
                As2[(buf ^ 1) * 16 * SAD + ak[t] * SAD + am[t]] = pack2(aReg[t], aReg[t]);
            cp_wait0();
            __syncthreads();
            buf ^= 1;
        }
    }

#pragma unroll
    for (int r = 0; r < 8; r++) {
        int row = rowBase + ty * 8 + r;
        float v[8];
#pragma unroll
        for (int c = 0; c < 4; c++) unpack2(acc2[r][c], v[2 * c], v[2 * c + 1]);
#pragma unroll
        for (int c = 0; c < 8; c++) {
            int col = colBase + tx * 8 + c;
            if (col < biasLimit) v[c] += bias[col];
            if (doElu) v[c] = elu_fast(v[c]);
        }
        float* p = C + (size_t)row * N + colBase + tx * 8;
        *(float4*)p       = make_float4(v[0], v[1], v[2], v[3]);
        *(float4*)(p + 4) = make_float4(v[4], v[5], v[6], v[7]);
    }
}

// ---------------- build [Wa-Wb | Wb] (128 x 256) from conv_w (256 x 128) ---
__global__ void build_wcat(const float* __restrict__ w, float* __restrict__ wc)
{
    int idx = blockIdx.x * 256 + threadIdx.x;
    int d = idx >> 8;
    int n = idx & 255;
    float v;
    if (n < 128) v = w[d * 128 + n] - w[(128 + d) * 128 + n];
    else         v = w[(128 + d) * 128 + (n - 128)];
    wc[idx] = v;
}

// ---------------- fused per-graph kNN + radix top-k + aggregate ------------
#define SXT_S 132
#define SD_S  132
#define SMEM_KNN ((128*SXT_S + 128*SD_S + 128*128 + 128 + 128*KNN) * 4)

__global__ __launch_bounds__(512, 1) void knn_agg(
    const float* __restrict__ X, const float* __restrict__ PQ,
    float* __restrict__ OUT)
{
    extern __shared__ float sm[];
    float* sXT = sm;                         // [f][n] stride 132
    float* sD  = sXT + 128 * SXT_S;          // [i][j] stride 132
    float* sQ  = sD  + 128 * SD_S;           // [n][f] stride 128
    float* sSq = sQ  + 128 * 128;            // [n]
    int*   sList = (int*)(sSq + 128);        // [i][24]

    const int g   = blockIdx.x;
    const int tid = threadIdx.x;
    const float* Xg  = X  + (size_t)g * NPG * HID;
    const float* PQg = PQ + (size_t)g * NPG * 2 * HID;

    // async copy of q tile (consumed only in phase 4)
#pragma unroll
    for (int t = 0; t < 8; t++) {
        int idx = t * 512 + tid;
        int n = idx >> 5, c4 = (idx & 31) * 4;
        cp16(&sQ[n * 128 + c4], &PQg[n * 256 + 128 + c4]);
    }
    cp_commit();

    // phase 1: load X (transposed)
    for (int idx = tid; idx < NPG * HID; idx += 512) {
        int n = idx >> 7, f = idx & 127;
        sXT[f * SXT_S + n] = Xg[idx];
    }
    __syncthreads();

    // phase 2: squared norms
    if (tid < 128) {
        float s = 0.0f;
#pragma unroll 8
        for (int d = 0; d < 128; d++) {
            float v = sXT[d * SXT_S + tid];
            s += v * v;
        }
        sSq[tid] = s;
    }
    __syncthreads();

    // phase 3: Gram across ALL 16 warps. Warp w owns rows w*8..w*8+8; each
    // lane owns 4 cols (l*4). acc pairs over ROWS (natural u64 from sXT),
    // B operand duplicated per-col.
    const int w = tid >> 5;
    const int l = tid & 31;
    {
        const int i0 = w * 8, j0 = l * 4;
        u64 acc2[4][4];   // [rowpair][col]
#pragma unroll
        for (int r = 0; r < 4; r++)
#pragma unroll
            for (int c = 0; c < 4; c++) acc2[r][c] = 0ull;

#pragma unroll 2
        for (int d = 0; d < 128; d++) {
            const float* rowp = sXT + d * SXT_S;
            const u64* ap = (const u64*)(rowp + i0);
            ulonglong2 a01 = *(const ulonglong2*)(ap);
            ulonglong2 a23 = *(const ulonglong2*)(ap + 2);
            u64 a[4] = {a01.x, a01.y, a23.x, a23.y};   // row pairs
            float4 bj = *(const float4*)(rowp + j0);
            u64 bd[4];
            bd[0] = pack2(bj.x, bj.x); bd[1] = pack2(bj.y, bj.y);
            bd[2] = pack2(bj.z, bj.z); bd[3] = pack2(bj.w, bj.w);
#pragma unroll
            for (int r = 0; r < 4; r++)
#pragma unroll
                for (int c = 0; c < 4; c++) dfma(acc2[r][c], a[r], bd[c]);
        }

        float sqj[4];
#pragma unroll
        for (int c = 0; c < 4; c++) sqj[c] = sSq[j0 + c];
#pragma unroll
        for (int r = 0; r < 4; r++) {
            int ia = i0 + 2 * r;
            float sqa = sSq[ia], sqb = sSq[ia + 1];
            float lo[4], hi[4];
#pragma unroll
            for (int c = 0; c < 4; c++) unpack2(acc2[r][c], lo[c], hi[c]);
            float4 v0, v1;
            v0.x = sqa + sqj[0] - 2.0f*lo[0]; v0.y = sqa + sqj[1] - 2.0f*lo[1];
            v0.z = sqa + sqj[2] - 2.0f*lo[2]; v0.w = sqa + sqj[3] - 2.0f*lo[3];
            v1.x = sqb + sqj[0] - 2.0f*hi[0]; v1.y = sqb + sqj[1] - 2.0f*hi[1];
            v1.z = sqb + sqj[2] - 2.0f*hi[2]; v1.w = sqb + sqj[3] - 2.0f*hi[3];
            *(float4*)&sD[ia * SD_S + j0]       = v0;
            *(float4*)&sD[(ia + 1) * SD_S + j0] = v1;
        }
    }
    cp_wait0();          // q tile in place
    __syncthreads();

    // phase 4: per-row radix-select threshold + neighbor list + aggregate
    const unsigned lmask = (1u << l) - 1u;
    const int rowBase = w * 8;

    for (int pp = 0; pp < 4; pp++) {
        const int iA = rowBase + 2 * pp;

        unsigned ka[2][4];
#pragma unroll
        for (int rr = 0; rr < 2; rr++)
#pragma unroll
            for (int c = 0; c < 4; c++)
                ka[rr][c] = fkey(sD[(iA + rr) * SD_S + l + 32 * c]);

        unsigned lo0 = 0, hi0 = 0xffffffffu, lo1 = 0, hi1 = 0xffffffffu;
#pragma unroll 1
        for (int it = 0; it < 32; it++) {
            unsigned m0 = lo0 + ((hi0 - lo0) >> 1);
            unsigned m1 = lo1 + ((hi1 - lo1) >> 1);
            int c0 = (ka[0][0] <= m0) + (ka[0][1] <= m0) + (ka[0][2] <= m0) + (ka[0][3] <= m0);
            int c1 = (ka[1][0] <= m1) + (ka[1][1] <= m1) + (ka[1][2] <= m1) + (ka[1][3] <= m1);
            c0 = __reduce_add_sync(0xffffffffu, c0);
            c1 = __reduce_add_sync(0xffffffffu, c1);
            if (c0 >= KNN) hi0 = m0; else lo0 = m0 + 1;
            if (c1 >= KNN) hi1 = m1; else lo1 = m1 + 1;
        }
        const unsigned KV[2] = {lo0, lo1};

#pragma unroll 1
        for (int rr = 0; rr < 2; rr++) {
            const int i = iA + rr;
            const unsigned kv = KV[rr];

            const int fo = 4 * l;
            float4 pv = *(const float4*)(PQg + (size_t)i * 256 + fo);

            int cl = 0;
#pragma unroll
            for (int c = 0; c < 4; c++) cl += (ka[rr][c] < kv) ? 1 : 0;
            int c0tot = __reduce_add_sync(0xffffffffu, cl);
            int rem = KNN - c0tot;

            bool sel[4];
#pragma unroll
            for (int c = 0; c < 4; c++) {
                bool eq = (ka[rr][c] == kv);
                unsigned bal = __ballot_sync(0xffffffffu, eq);
                int before = __popc(bal & lmask);
                sel[c] = (ka[rr][c] < kv) || (eq && before < rem);
                rem -= __popc(bal);
            }
            int base = 0;
#pragma unroll
            for (int c = 0; c < 4; c++) {
                unsigned bs = __ballot_sync(0xffffffffu, sel[c]);
                if (sel[c]) sList[i * KNN + base + __popc(bs & lmask)] = l + 32 * c;
                base += __popc(bs);
            }
            __syncwarp();

            float4 qm = make_float4(-3.0e38f, -3.0e38f, -3.0e38f, -3.0e38f);
#pragma unroll 4
            for (int it = 0; it < KNN; it++) {
                int j = sList[i * KNN + it];
                float4 qv = *(const float4*)(sQ + j * 128 + fo);
                qm.x = fmaxf(qm.x, qv.x);
                qm.y = fmaxf(qm.y, qv.y);
                qm.z = fmaxf(qm.z, qv.z);
                qm.w = fmaxf(qm.w, qv.w);
            }
            float4 ov;
            ov.x = elu_fast(pv.x + qm.x);
            ov.y = elu_fast(pv.y + qm.y);
            ov.z = elu_fast(pv.z + qm.z);
            ov.w = elu_fast(pv.w + qm.w);
            *(float4*)(OUT + ((size_t)g * NPG + i) * HID + fo) = ov;
        }
    }
}

// ---------------- sum-pool + output MLP -------------------------------------
__global__ __launch_bounds__(128) void pool_mlp(
    const float* __restrict__ X,
    const float* __restrict__ w1, const float* __restrict__ b1,
    const float* __restrict__ w2, const float* __restrict__ b2,
    const float* __restrict__ w3, const float* __restrict__ b3,
    const float* __restrict__ w4, const float* __restrict__ b4,
    float* __restrict__ out)
{
    __shared__ float pooled[128];
    __shared__ float o1[64];
    __shared__ float o2[32];
    __shared__ float o3[32];
    const int g = blockIdx.x, t = threadIdx.x;
    const float* Xg = X + (size_t)g * NPG * HID;

    float s = 0.0f;
    for (int n = 0; n < NPG; n++) s += Xg[n * HID + t];
    pooled[t] = s;
    __syncthreads();

    if (t < 64) {
        float a = b1[t];
        for (int d = 0; d < 128; d++) a += pooled[d] * w1[d * 64 + t];
        o1[t] = elu_fast(a);
    }
    __syncthreads();
    if (t < 32) {
        float a = b2[t];
        for (int d = 0; d < 64; d++) a += o1[d] * w2[d * 32 + t];
        o2[t] = elu_fast(a);
    }
    __syncthreads();
    if (t < 32) {
        float a = b3[t];
        for (int d = 0; d < 32; d++) a += o2[d] * w3[d * 32 + t];
        o3[t] = elu_fast(a);
    }
    __syncthreads();
    if (t < 6) {
        float a = b4[t];
        for (int d = 0; d < 32; d++) a += o3[d] * w4[d * 6 + t];
        out[g * 6 + t] = a;
    }
}

__global__ void copy_batch(const int* __restrict__ b, float* __restrict__ out)
{
    int i = blockIdx.x * 256 + threadIdx.x;
    if (i < NODES) out[i] = (float)b[i];
}

// ---------------------------------------------------------------------------
extern "C" void kernel_launch(void* const* d_in, const int* in_sizes, int n_in,
                              void* d_out, int out_size)
{
    const float* x_pf    = (const float*)d_in[0];
    const float* enc_w1  = (const float*)d_in[1];
    const float* enc_b1  = (const float*)d_in[2];
    const float* enc_w2  = (const float*)d_in[3];
    const float* enc_b2  = (const float*)d_in[4];
    const float* conv_w[3] = {(const float*)d_in[5], (const float*)d_in[7], (const float*)d_in[9]};
    const float* conv_b[3] = {(const float*)d_in[6], (const float*)d_in[8], (const float*)d_in[10]};
    const float* out_w1  = (const float*)d_in[11];
    const float* out_b1  = (const float*)d_in[12];
    const float* out_w2  = (const float*)d_in[13];
    const float* out_b2  = (const float*)d_in[14];
    const float* out_w3  = (const float*)d_in[15];
    const float* out_b3  = (const float*)d_in[16];
    const float* out_w4  = (const float*)d_in[17];
    const float* out_b4  = (const float*)d_in[18];
    const int*   batch   = (const int*)d_in[19];

    float *featA, *featB, *pq, *wc;
    cudaGetSymbolAddress((void**)&featA, g_feat_a);
    cudaGetSymbolAddress((void**)&featB, g_feat_b);
    cudaGetSymbolAddress((void**)&pq,    g_pq);
    cudaGetSymbolAddress((void**)&wc,    g_wc);

    cudaFuncSetAttribute(mm_kernel, cudaFuncAttributeMaxDynamicSharedMemorySize, MM_SMEM);
    cudaFuncSetAttribute(knn_agg,   cudaFuncAttributeMaxDynamicSharedMemorySize, SMEM_KNN);

    // encoder
    mm_kernel<<<dim3(NODES / 128, 1), 256, MM_SMEM>>>(x_pf,  enc_w1, enc_b1, 128, 1, featB, NODES, 128, 16);
    mm_kernel<<<dim3(NODES / 128, 1), 256, MM_SMEM>>>(featB, enc_w2, enc_b2, 128, 1, featA, NODES, 128, 128);

    // 3 dynamic edge convs
    float* cur = featA;
    float* nxt = featB;
    for (int cidx = 0; cidx < 3; cidx++) {
        build_wcat<<<128, 256>>>(conv_w[cidx], wc);
        mm_kernel<<<dim3(NODES / 128, 2), 256, MM_SMEM>>>(cur, wc, conv_b[cidx], 128, 0, pq, NODES, 256, 128);
        knn_agg<<<NG, 512, SMEM_KNN>>>(cur, pq, nxt);
        float* t = cur; cur = nxt; nxt = t;
    }

    pool_mlp<<<NG, 128>>>(cur, out_w1, out_b1, out_w2, out_b2,
                          out_w3, out_b3, out_w4, out_b4, (float*)d_out);

    copy_batch<<<(NODES + 255) / 256, 256>>>(batch, (float*)d_out + NG * 6);
}